// round 6
// baseline (speedup 1.0000x reference)
#include <cuda_runtime.h>
#include <cuda_bf16.h>
#include <cstdint>

#define BATCH  512
#define NP1    257
#define DP1    129
#define NLAYER 4
#define ZST    152     // Zh smem row stride (halves)
#define GST    152     // G/S/W smem row stride
#define AST    129     // acc smem row stride (scalar access only)
#define NTHR   576     // 18 warps: 3 (M, 48) x 6 (N, 24)

typedef __nv_bfloat16 bf16;

__device__ bf16 g_PQ[NLAYER * 2 * 128 * 128];   // bf16 P,Q weights

// ------------------------------ mma helpers --------------------------------
__device__ __forceinline__ uint32_t smaddr(const void* p) {
    return (uint32_t)__cvta_generic_to_shared(p);
}
__device__ __forceinline__ void ldmx4(uint32_t* r, uint32_t a) {
    asm volatile("ldmatrix.sync.aligned.m8n8.x4.shared.b16 {%0,%1,%2,%3}, [%4];"
                 : "=r"(r[0]), "=r"(r[1]), "=r"(r[2]), "=r"(r[3]) : "r"(a));
}
__device__ __forceinline__ void ldmx4t(uint32_t* r, uint32_t a) {
    asm volatile("ldmatrix.sync.aligned.m8n8.x4.trans.shared.b16 {%0,%1,%2,%3}, [%4];"
                 : "=r"(r[0]), "=r"(r[1]), "=r"(r[2]), "=r"(r[3]) : "r"(a));
}
__device__ __forceinline__ void ldmx2t(uint32_t* r, uint32_t a) {
    asm volatile("ldmatrix.sync.aligned.m8n8.x2.trans.shared.b16 {%0,%1}, [%2];"
                 : "=r"(r[0]), "=r"(r[1]) : "r"(a));
}
__device__ __forceinline__ void mma16816(float* c, const uint32_t* a, const uint32_t* b) {
    asm volatile("mma.sync.aligned.m16n8k16.row.col.f32.bf16.bf16.f32 "
                 "{%0,%1,%2,%3}, {%4,%5,%6,%7}, {%8,%9}, {%0,%1,%2,%3};"
                 : "+f"(c[0]), "+f"(c[1]), "+f"(c[2]), "+f"(c[3])
                 : "r"(a[0]), "r"(a[1]), "r"(a[2]), "r"(a[3]), "r"(b[0]), "r"(b[1]));
}
__device__ __forceinline__ __nv_bfloat162 pack2(float a, float b) {
    __nv_bfloat162 v;
    v.x = __float2bfloat16(a);
    v.y = __float2bfloat16(b);
    return v;
}

// ------------------------------- convPQ -------------------------------------
__global__ void k_convPQ(const float* __restrict__ allparam) {
    int i = blockIdx.x * blockDim.x + threadIdx.x;
    if (i < NLAYER * 2 * 128 * 128) g_PQ[i] = __float2bfloat16(allparam[i]);
}

// ------------------------------- k_fused ------------------------------------
extern __shared__ bf16 sm_f[];

__global__ __launch_bounds__(NTHR, 1) void k_fused(const float* __restrict__ Zin0,
                                                   const float* __restrict__ gamma,
                                                   float* __restrict__ Zio) {
    bf16* Zh = sm_f;                       // 257 x 152
    bf16* Gs = Zh + 257 * ZST;             // 144 x 152  (Gram, later W)
    bf16* Ss = Gs + 144 * GST;             // 144 x 152  (S = G P^T)
    bf16* Ac = Ss + 144 * GST;             // 257 x 129  (bf16 running acc)

    int b = blockIdx.x;
    const float* Zb0 = Zin0 + (size_t)b * NP1 * DP1;
    float*       Zo  = Zio  + (size_t)b * NP1 * DP1;

    int tid = threadIdx.x, lane = tid & 31, warp = tid >> 5;
    int wmo = (warp % 3) * 48;     // M-tile origin
    int wno = (warp / 3) * 24;     // N-tile origin
    int mat = lane >> 3, l7 = lane & 7, l16 = lane & 15;
    int g = lane >> 2, t4 = lane & 3;

    // ---------------- init: Zh from input Z; acc = 0 ----------------
    for (int i = tid; i < 257 * 38; i += NTHR) {
        int r = i / 38, c4 = (i % 38) * 4;
#pragma unroll
        for (int u = 0; u < 4; u++) {
            int j = c4 + u;
            float v = (j < DP1) ? Zb0[(size_t)r * DP1 + j] : 0.0f;
            Zh[r * ZST + j] = __float2bfloat16(v);
        }
    }
    for (int i = tid; i < 257 * AST; i += NTHR)
        Ac[i] = __float2bfloat16(0.0f);
    __syncthreads();

    float acc[3][3][4];            // [mi][nb][elem] : 48 x 24 warp tile
    uint32_t afr[3][4], bfr[3][2];

    auto zero_acc = [&]() {
#pragma unroll
        for (int a = 0; a < 3; a++)
#pragma unroll
            for (int c = 0; c < 3; c++)
#pragma unroll
                for (int e = 0; e < 4; e++) acc[a][c][e] = 0.0f;
    };
    auto do_mmas = [&]() {
#pragma unroll
        for (int nb = 0; nb < 3; nb++)
#pragma unroll
            for (int mi = 0; mi < 3; mi++)
                mma16816(acc[mi][nb], afr[mi], bfr[nb]);
    };
    // B trans fragment loaders from an smem matrix (stride st): cols wno..wno+23
    auto loadB_tr = [&](const bf16* base, int st, int kk) {
        uint32_t t[4];
        int brow = kk + ((mat & 1) << 3) + l7;
        ldmx4t(t, smaddr(&base[brow * st + wno + ((mat >> 1) << 3)]));
        bfr[0][0] = t[0]; bfr[0][1] = t[1];
        bfr[1][0] = t[2]; bfr[1][1] = t[3];
        int brow2 = kk + l16;
        ldmx2t(bfr[2], smaddr(&base[brow2 * st + wno + 16]));
    };

    for (int l = 0; l < NLAYER; l++) {
        const bf16* P = g_PQ + ((size_t)l * 2 + 0) * 128 * 128;
        const bf16* Q = g_PQ + ((size_t)l * 2 + 1) * 128 * 128;
        const float* gml = gamma + (size_t)l * NP1 * DP1;
        const float* Zi  = (l == 0) ? Zb0 : Zo;

        // ================= Phase 1: G = Zh[:256]^T Zh[:256] =================
        zero_acc();
        for (int kk = 0; kk < 256; kk += 16) {
            int arow = kk + ((mat >> 1) << 3) + l7;
#pragma unroll
            for (int mi = 0; mi < 3; mi++)
                ldmx4t(afr[mi], smaddr(&Zh[arow * ZST + wmo + mi * 16 + ((mat & 1) << 3)]));
            loadB_tr(Zh, ZST, kk);
            do_mmas();
        }
#pragma unroll
        for (int mi = 0; mi < 3; mi++)
#pragma unroll
            for (int nb = 0; nb < 3; nb++) {
                float* c = acc[mi][nb];
                int row = wmo + mi * 16 + g;
                int col = wno + nb * 8 + 2 * t4;
                *(__nv_bfloat162*)&Gs[row * GST + col]       = pack2(c[0], c[1]);
                *(__nv_bfloat162*)&Gs[(row + 8) * GST + col] = pack2(c[2], c[3]);
            }
        __syncthreads();

        // ================= Phase 2a: S = G @ P^T  (K=128) =================
        zero_acc();
        for (int kk = 0; kk < 128; kk += 16) {
#pragma unroll
            for (int mi = 0; mi < 3; mi++) {
                int arow = wmo + mi * 16 + ((mat & 1) << 3) + l7;
                ldmx4(afr[mi], smaddr(&Gs[arow * GST + kk + ((mat >> 1) << 3)]));
            }
#pragma unroll
            for (int nb = 0; nb < 3; nb++) {
                int j = wno + nb * 8 + g;     // P row (n dim)
                if (j < 128) {
                    bfr[nb][0] = *(const uint32_t*)&P[j * 128 + kk + 2 * t4];
                    bfr[nb][1] = *(const uint32_t*)&P[j * 128 + kk + 8 + 2 * t4];
                } else {
                    bfr[nb][0] = 0u;
                    bfr[nb][1] = 0u;
                }
            }
            do_mmas();
        }
        // store S; fold in S[:,128] = G[:,128] (P_full's unit corner column)
#pragma unroll
        for (int mi = 0; mi < 3; mi++)
#pragma unroll
            for (int nb = 0; nb < 3; nb++) {
                float* c = acc[mi][nb];
                int row = wmo + mi * 16 + g;
                int col = wno + nb * 8 + 2 * t4;
                __nv_bfloat162 v0 = pack2(c[0], c[1]);
                __nv_bfloat162 v1 = pack2(c[2], c[3]);
                if (col == 128) {
                    v0.x = Gs[row * GST + 128];
                    v1.x = Gs[(row + 8) * GST + 128];
                }
                *(__nv_bfloat162*)&Ss[row * GST + col]       = v0;
                *(__nv_bfloat162*)&Ss[(row + 8) * GST + col] = v1;
            }
        __syncthreads();

        // ================= Phase 2b: W = Q @ S  (K=128, into Gs) ============
        zero_acc();
        for (int kk = 0; kk < 128; kk += 16) {
#pragma unroll
            for (int mi = 0; mi < 3; mi++) {
                int m = wmo + mi * 16 + g;
                afr[mi][0] = (m     < 128) ? *(const uint32_t*)&Q[m * 128 + kk + 2 * t4]           : 0u;
                afr[mi][1] = (m + 8 < 128) ? *(const uint32_t*)&Q[(m + 8) * 128 + kk + 2 * t4]     : 0u;
                afr[mi][2] = (m     < 128) ? *(const uint32_t*)&Q[m * 128 + kk + 8 + 2 * t4]       : 0u;
                afr[mi][3] = (m + 8 < 128) ? *(const uint32_t*)&Q[(m + 8) * 128 + kk + 8 + 2 * t4] : 0u;
            }
            loadB_tr(Ss, GST, kk);
            do_mmas();
        }
#pragma unroll
        for (int mi = 0; mi < 3; mi++)
#pragma unroll
            for (int nb = 0; nb < 3; nb++) {
                float* c = acc[mi][nb];
                int row = wmo + mi * 16 + g;
                int col = wno + nb * 8 + 2 * t4;
                *(__nv_bfloat162*)&Gs[row * GST + col]       = pack2(c[0], c[1]);
                *(__nv_bfloat162*)&Gs[(row + 8) * GST + col] = pack2(c[2], c[3]);
            }
        __syncthreads();

        // ================= Phase 3: R = Zh @ W / 256; update ================
        // chunk 0: rows 0..143 ; chunk 1: rows 113..256 (outputs <144 dropped)
#pragma unroll
        for (int c0 = 0; c0 < 2; c0++) {
            int base = c0 ? 113 : 0;
            zero_acc();
            for (int kk = 0; kk < 144; kk += 16) {
#pragma unroll
                for (int mi = 0; mi < 3; mi++) {
                    int arow = base + wmo + mi * 16 + ((mat & 1) << 3) + l7;
                    ldmx4(afr[mi], smaddr(&Zh[arow * ZST + kk + ((mat >> 1) << 3)]));
                }
                loadB_tr(Gs, GST, kk);
                do_mmas();
            }
            __syncthreads();   // all chunk GEMM reads of Zh done before writes

            const float inv = 1.0f / 256.0f;
#pragma unroll
            for (int mi = 0; mi < 3; mi++)
#pragma unroll
                for (int nb = 0; nb < 3; nb++) {
                    float* cc = acc[mi][nb];
                    int row0 = wmo + mi * 16 + g;
                    int col0 = wno + nb * 8 + 2 * t4;
#pragma unroll
                    for (int e = 0; e < 4; e++) {
                        int n = base + row0 + ((e >> 1) ? 8 : 0);
                        int j = col0 + (e & 1);
                        if (n < NP1 && j < DP1 && (c0 == 0 || n >= 144)) {
                            size_t fi = (size_t)n * DP1 + j;
                            float r = cc[e] * inv;
                            float a = __bfloat162float(Ac[n * AST + j]);
                            float zo = Zi[fi] + r + a;
                            Zo[fi] = zo;
                            Ac[n * AST + j] =
                                __float2bfloat16(a + r * gml[fi]);
                            Zh[n * ZST + j] = __float2bfloat16(zo);
                        }
                    }
                }
            __syncthreads();
        }
    }
}

// ------------------------------ kernel_launch -------------------------------
extern "C" void kernel_launch(void* const* d_in, const int* in_sizes, int n_in,
                              void* d_out, int out_size) {
    const float* Z        = (const float*)d_in[0];
    const float* allparam = (const float*)d_in[1];
    const float* gamma    = (const float*)d_in[2];

    const int smem_bytes = (257 * ZST + 2 * 144 * GST + 257 * AST) * (int)sizeof(bf16);
    cudaFuncSetAttribute(k_fused, cudaFuncAttributeMaxDynamicSharedMemorySize,
                         smem_bytes);

    k_convPQ<<<(NLAYER * 2 * 128 * 128 + 255) / 256, 256>>>(allparam);
    k_fused<<<BATCH, NTHR, smem_bytes>>>(Z, gamma, (float*)d_out);
}